// round 15
// baseline (speedup 1.0000x reference)
#include <cuda_runtime.h>
#include <cuda_fp16.h>
#include <math.h>
#include <stdint.h>

#define Bq 4
#define Lq 8192
#define Dq 1024
#define Nq (Bq*Lq)        // 32768 rows
#define KCONV 4
#define NC 64             // scan chunks per sequence (Lq/LC)
#define LC 128            // == GEMM row-tile M

// ---------------- scratch (device globals; no cudaMalloc allowed) ----------
__device__ __half  g_xch [(size_t)Nq*Dq];   // x_conv fp16  (later: h fp16)
__device__ __half2 g_hap [(size_t)Nq*Dq];   // (h_local, apre) fp16 pairs; later y fp16
__device__ float g_aggP[Bq*NC*Dq];
__device__ float g_aggS[Bq*NC*Dq];
__device__ float g_carry[Bq*NC*Dq];
__device__ __half g_Wrh[(size_t)Dq*Dq];
__device__ __half g_Wih[(size_t)Dq*Dq];
__device__ __half g_Woh[(size_t)Dq*Dq];

// ---------------- PTX helpers (all sm_80-compatible) ------------------------
__device__ __forceinline__ uint32_t smem_u32(const void* p) {
    uint32_t a;
    asm("{ .reg .u64 t; cvta.to.shared.u64 t, %1; cvt.u32.u64 %0, t; }" : "=r"(a) : "l"(p));
    return a;
}
__device__ __forceinline__ void ldsm4(uint32_t (&r)[4], uint32_t addr) {
    asm volatile("ldmatrix.sync.aligned.m8n8.x4.shared.b16 {%0,%1,%2,%3}, [%4];"
        : "=r"(r[0]), "=r"(r[1]), "=r"(r[2]), "=r"(r[3]) : "r"(addr));
}
__device__ __forceinline__ void mma16816(float (&d)[4], const uint32_t (&a)[4],
                                         uint32_t b0, uint32_t b1) {
    asm volatile("mma.sync.aligned.m16n8k16.row.col.f32.f16.f16.f32 "
        "{%0,%1,%2,%3}, {%4,%5,%6,%7}, {%8,%9}, {%0,%1,%2,%3};"
        : "+f"(d[0]), "+f"(d[1]), "+f"(d[2]), "+f"(d[3])
        : "r"(a[0]), "r"(a[1]), "r"(a[2]), "r"(a[3]), "r"(b0), "r"(b1));
}
__device__ __forceinline__ void cpasync16(uint32_t saddr, const void* g) {
    asm volatile("cp.async.cg.shared.global [%0], [%1], 16;" :: "r"(saddr), "l"(g));
}
// L1-allocating variant: use for A tiles shared by the 2 co-resident CTAs (same m0)
__device__ __forceinline__ void cpasync16ca(uint32_t saddr, const void* g) {
    asm volatile("cp.async.ca.shared.global [%0], [%1], 16;" :: "r"(saddr), "l"(g));
}
#define CP_COMMIT() asm volatile("cp.async.commit_group;" ::: "memory")
__device__ __forceinline__ uint32_t sw128(uint32_t off) { return off ^ ((off >> 3) & 0x70); }

// ============================================================
// 0+1) fused: weight prep (fp32->fp16) + causal depthwise conv
//      first WPREP_BLOCKS blocks convert W; the rest run conv (16 l/thread)
// ============================================================
#define WPREP_BLOCKS (3 * Dq * Dq / 4 / 256)              // 3072
#define CONV_BLOCKS  ((Bq * (Lq / 16) * (Dq / 4) + 255) / 256)

__global__ void conv_prep_kernel(const float* __restrict__ x,
                                 const float* __restrict__ w,
                                 const float* __restrict__ bias,
                                 const float* __restrict__ Wr,
                                 const float* __restrict__ Wi,
                                 const float* __restrict__ Wo) {
    if (blockIdx.x < WPREP_BLOCKS) {
        int i = blockIdx.x * blockDim.x + threadIdx.x;    // float4 index
        const int Q = Dq * Dq / 4;
        int wsel = i / Q;
        int off = i - wsel * Q;
        const float4* src = (wsel == 0) ? (const float4*)Wr
                          : (wsel == 1) ? (const float4*)Wi : (const float4*)Wo;
        __half* dst = (wsel == 0) ? g_Wrh : (wsel == 1) ? g_Wih : g_Woh;
        float4 v = src[off];
        __half2 p0 = __floats2half2_rn(v.x, v.y);
        __half2 p1 = __floats2half2_rn(v.z, v.w);
        uint2 hv;
        hv.x = *(uint32_t*)&p0;
        hv.y = *(uint32_t*)&p1;
        ((uint2*)dst)[off] = hv;
        return;
    }

    const int D4 = Dq / 4;
    const int LG = Lq / 16;                // l-groups per sequence
    int t = (blockIdx.x - WPREP_BLOCKS) * blockDim.x + threadIdx.x;
    if (t >= Bq * LG * D4) return;
    int d4 = t % D4;
    int g  = t / D4;
    int b  = g / LG;
    int l0 = (g % LG) * 16;
    int n0 = b * Lq + l0;                  // first output row

    float wv[4][4];
    const float* wp = w + d4 * 16;
    #pragma unroll
    for (int dl = 0; dl < 4; dl++)
        #pragma unroll
        for (int k = 0; k < 4; k++) wv[dl][k] = wp[dl * 4 + k];
    float4 bb = ((const float4*)bias)[d4];

    // window rows l0-3 .. l0+15  (19 loads for 16 outputs)
    float4 xv[19];
    #pragma unroll
    for (int j = 0; j < 19; j++) {
        int l = l0 - 3 + j;
        if (l < 0) xv[j] = make_float4(0.f, 0.f, 0.f, 0.f);
        else       xv[j] = ((const float4*)x)[(size_t)(b * Lq + l) * D4 + d4];
    }

    #pragma unroll
    for (int i = 0; i < 16; i++) {
        float a0 = bb.x, a1 = bb.y, a2 = bb.z, a3 = bb.w;
        #pragma unroll
        for (int k = 0; k < 4; k++) {
            float4 v = xv[i + k];
            a0 = fmaf(v.x, wv[0][k], a0);
            a1 = fmaf(v.y, wv[1][k], a1);
            a2 = fmaf(v.z, wv[2][k], a2);
            a3 = fmaf(v.w, wv[3][k], a3);
        }
        __half2 p0 = __floats2half2_rn(a0, a1);
        __half2 p1 = __floats2half2_rn(a2, a3);
        uint2 hv;
        hv.x = *(uint32_t*)&p0;
        hv.y = *(uint32_t*)&p1;
        ((uint2*)g_xch)[(size_t)(n0 + i) * D4 + d4] = hv;
    }
}

// ============================================================
// 2) dual GEMM (r & i, fp16) + fused conv-recompute + gates + local scan
//    tile M=128, N=64.  Per stage BK=64: A 16K | Br 8K | Bi 8K = 32K, x3 stages
//    2 CTAs / SM; A loads via .ca (co-resident CTAs share m0 -> L1 reuse)
// ============================================================
#define RI_STAGE 32768
#define RI_SMEM  102400

__global__ __launch_bounds__(256, 2)
void gemm_ri_tc(const float* __restrict__ x,
                const float* __restrict__ cw, const float* __restrict__ cb,
                const float* __restrict__ Wrb, const float* __restrict__ Wib,
                const float* __restrict__ log_a) {
    extern __shared__ char smem[];
    __shared__ float  s_logab[64], s_rb[64], s_ib[64], s_cb[64];
    __shared__ float4 s_cw[64];
    __shared__ float  sPc[4][64], sSc[4][64];
    uint32_t sb = smem_u32(smem);
    int tid = threadIdx.x, wid = tid >> 5, lane = tid & 31;
    int m0 = blockIdx.y * 128;
    int n0 = blockIdx.x * 64;

    if (tid < 64) {
        float la = __ldg(&log_a[n0 + tid]);
        s_logab[tid] = -log1pf(expf(-la));     // ln(sigmoid(la)), tiny negative
        s_rb[tid]    = __ldg(&Wrb[n0 + tid]);
        s_ib[tid]    = __ldg(&Wib[n0 + tid]);
        s_cb[tid]    = __ldg(&cb[n0 + tid]);
        s_cw[tid]    = ((const float4*)cw)[n0 + tid];
    }

    float accR[2][4][4] = {}, accI[2][4][4] = {};

    auto issue = [&](int c) {
        uint32_t st = sb + (uint32_t)(c % 3) * RI_STAGE;
        int k0 = c * 64;
        #pragma unroll
        for (int t = 0; t < 4; t++) {           // A: 128 rows x 8 granules (.ca: shared with co-CTA)
            int idx = tid + t * 256;
            int r = idx >> 3, g = idx & 7;
            cpasync16ca(st + sw128(r * 128 + g * 16),
                        g_xch + (size_t)(m0 + r) * Dq + k0 + g * 8);
        }
        #pragma unroll
        for (int t = 0; t < 4; t++) {           // Br,Bi: 64 rows x 8 granules each
            int idx = tid + t * 256;
            int sel = idx >> 9, r = (idx >> 3) & 63, g = idx & 7;
            const __half* W = sel ? g_Wih : g_Wrh;
            cpasync16(st + 16384 + sel * 8192 + sw128(r * 128 + g * 16),
                      W + (size_t)(n0 + r) * Dq + k0 + g * 8);
        }
    };

    int wm0 = (wid >> 1) * 32;
    int wn0 = (wid & 1) * 32;
    uint32_t aRowB = (uint32_t)(wm0 + (lane & 15)) * 128;
    uint32_t aColB = (uint32_t)(lane >> 4) * 16;
    uint32_t bRowB = (uint32_t)(wn0 + ((lane >> 4) << 3) + (lane & 7)) * 128;
    uint32_t bColB = (uint32_t)((lane >> 3) & 1) * 16;

    issue(0); CP_COMMIT();
    issue(1); CP_COMMIT();

    #pragma unroll 1
    for (int c = 0; c < 16; ++c) {
        if (c < 15) asm volatile("cp.async.wait_group 1;" ::: "memory");
        else        asm volatile("cp.async.wait_group 0;" ::: "memory");
        __syncthreads();
        uint32_t st = sb + (uint32_t)(c % 3) * RI_STAGE;
        #pragma unroll
        for (int ks = 0; ks < 4; ++ks) {
            uint32_t ka = (uint32_t)ks * 32;
            uint32_t a0[4], a1[4], br[2][4], bi[2][4];
            ldsm4(a0, st + sw128(aRowB + ka + aColB));
            ldsm4(a1, st + sw128(aRowB + 2048 + ka + aColB));
            ldsm4(br[0], st + 16384 + sw128(bRowB + ka + bColB));
            ldsm4(br[1], st + 16384 + sw128(bRowB + 2048 + ka + bColB));
            ldsm4(bi[0], st + 24576 + sw128(bRowB + ka + bColB));
            ldsm4(bi[1], st + 24576 + sw128(bRowB + 2048 + ka + bColB));
            #pragma unroll
            for (int j = 0; j < 4; ++j) {
                int nb = j >> 1, hh = (j & 1) * 2;
                mma16816(accR[0][j], a0, br[nb][hh], br[nb][hh + 1]);
                mma16816(accR[1][j], a1, br[nb][hh], br[nb][hh + 1]);
                mma16816(accI[0][j], a0, bi[nb][hh], bi[nb][hh + 1]);
                mma16816(accI[1][j], a1, bi[nb][hh], bi[nb][hh + 1]);
            }
        }
        if (c < 14) { issue(c + 2); CP_COMMIT(); }
        __syncthreads();
    }

    // ---- epilogue overlay
    float* a_s = (float*)smem;            // [128][65]
    float* b_s = a_s + 128 * 65;          // [128][65]
    float* xs  = b_s + 128 * 65;          // [131][68] raw x tile (rows m0-3..m0+127)

    int bat0 = (m0 >> 13) << 13;          // first row of this sequence
    #pragma unroll
    for (int t = 0; t < 9; t++) {
        int idx = tid + t * 256;          // 131*16 = 2096 float4 loads
        if (idx < 131 * 16) {
            int j = idx >> 4, c4 = idx & 15;
            int gr = m0 - 3 + j;
            float4 v = make_float4(0.f, 0.f, 0.f, 0.f);
            if (gr >= bat0) v = *(const float4*)&x[(size_t)gr * Dq + n0 + c4 * 4];
            float* dst = &xs[j * 68 + c4 * 4];
            dst[0] = v.x; dst[1] = v.y; dst[2] = v.z; dst[3] = v.w;
        }
    }
    __syncthreads();

    #pragma unroll
    for (int tm = 0; tm < 2; tm++)
        #pragma unroll
        for (int j = 0; j < 4; j++) {
            int colb = wn0 + j * 8 + (lane & 3) * 2;
            #pragma unroll
            for (int e = 0; e < 4; e++) {
                int row = wm0 + tm * 16 + (lane >> 2) + (e >> 1) * 8;
                int col = colb + (e & 1);
                float4 wv = s_cw[col];
                float xcv = s_cb[col];
                xcv = fmaf(xs[(row + 0) * 68 + col], wv.x, xcv);
                xcv = fmaf(xs[(row + 1) * 68 + col], wv.y, xcv);
                xcv = fmaf(xs[(row + 2) * 68 + col], wv.z, xcv);
                xcv = fmaf(xs[(row + 3) * 68 + col], wv.w, xcv);
                float log_ab = s_logab[col];
                float crv = accR[tm][j][e] + s_rb[col];
                float civ = accI[tm][j][e] + s_ib[col];
                float r  = __fdividef(1.f, 1.f + __expf(-crv));
                float ii = __fdividef(1.f, 1.f + __expf(-civ));
                float t  = 8.f * r * log_ab;               // in (-0.00443, 0]
                // exp(t) and -expm1(2t): 3-term polys, exact to <3e-8 rel in range
                float a  = 1.f + t * (1.f + t * (0.5f + t * (1.f / 6.f)));
                float u  = 2.f * t;
                float om = -(u * (1.f + u * (0.5f + u * (1.f / 6.f))));
                om = fmaxf(om, 1e-6f);
                float bt = sqrtf(om) * ii * xcv;
                a_s[row * 65 + col] = a;
                b_s[row * 65 + col] = bt;
            }
        }
    __syncthreads();

    // ---- parallel local scan: 4 segments of 32 rows x 64 cols (fp32 math, fp16 store)
    {
        int seg = tid >> 6, cc = tid & 63;
        float P = 1.f, S = 0.f;
        #pragma unroll 8
        for (int l = seg * 32; l < seg * 32 + 32; l++) {
            float a = a_s[l * 65 + cc], b = b_s[l * 65 + cc];
            S = fmaf(a, S, b);
            P *= a;
        }
        sPc[seg][cc] = P; sSc[seg][cc] = S;
        __syncthreads();
        float cS = 0.f, cP = 1.f;
        #pragma unroll
        for (int g = 0; g < 3; g++)
            if (g < seg) { cS = fmaf(sPc[g][cc], cS, sSc[g][cc]); cP *= sPc[g][cc]; }
        float h = cS, Ap = cP;
        size_t gb = (size_t)(m0 + seg * 32) * Dq + n0 + cc;
        #pragma unroll 8
        for (int l = 0; l < 32; l++) {
            float a = a_s[(seg * 32 + l) * 65 + cc], b = b_s[(seg * 32 + l) * 65 + cc];
            h = fmaf(a, h, b);
            Ap *= a;
            g_hap[gb + (size_t)l * Dq] =
                __halves2half2(__float2half_rn(h), __float2half_rn(Ap));
        }
        if (seg == 3) {
            int bat = m0 >> 13, chk = (m0 & 8191) >> 7;
            int ai = (bat * NC + chk) * Dq + n0 + cc;
            g_aggP[ai] = Ap;
            g_aggS[ai] = h;
        }
    }
}

// ============================================================
// 3) inter-chunk scan (parallel: 8-chunk serial compose + smem combine)
// ============================================================
__global__ __launch_bounds__(512)
void scan2_kernel() {
    __shared__ float sP[8][65], sS[8][65];
    int d0 = blockIdx.x * 64;
    int b  = blockIdx.z;
    int d  = threadIdx.x & 63;
    int cg = threadIdx.x >> 6;            // 0..7

    float locP[8], locS[8];
    float P = 1.f, S = 0.f;
    #pragma unroll
    for (int j = 0; j < 8; j++) {
        int ai = (b * NC + cg * 8 + j) * Dq + d0 + d;
        locP[j] = g_aggP[ai];
        locS[j] = g_aggS[ai];
        S = fmaf(locP[j], S, locS[j]);
        P *= locP[j];
    }
    sP[cg][d] = P; sS[cg][d] = S;
    __syncthreads();

    float carry = 0.f;                    // exclusive combine over lower groups
    #pragma unroll
    for (int g = 0; g < 7; g++)
        if (g < cg) carry = fmaf(sP[g][d], carry, sS[g][d]);

    #pragma unroll
    for (int j = 0; j < 8; j++) {
        int ai = (b * NC + cg * 8 + j) * Dq + d0 + d;
        g_carry[ai] = carry;
        carry = fmaf(locP[j], carry, locS[j]);
    }
}

// ============================================================
// 3b) elementwise fixup -> h (fp16 into g_xch); reads (h,ap) pairs
// ============================================================
__global__ void scan3_kernel() {
    const int D4 = Dq / 4;
    size_t i = (size_t)blockIdx.x * blockDim.x + threadIdx.x;  // 4 elems each
    int d4  = (int)(i % D4);
    int row = (int)(i / D4);
    int bat = row >> 13;
    int chk = (row & 8191) >> 7;
    const float4 cy = *(const float4*)&g_carry[(bat * NC + chk) * Dq + d4 * 4];
    uint4 pv = ((const uint4*)g_hap)[i];     // 4 (h, ap) half2 pairs
    float2 e0 = __half22float2(*(__half2*)&pv.x);
    float2 e1 = __half22float2(*(__half2*)&pv.y);
    float2 e2 = __half22float2(*(__half2*)&pv.z);
    float2 e3 = __half22float2(*(__half2*)&pv.w);
    float h0 = fmaf(cy.x, e0.y, e0.x);
    float h1 = fmaf(cy.y, e1.y, e1.x);
    float h2 = fmaf(cy.z, e2.y, e2.x);
    float h3 = fmaf(cy.w, e3.y, e3.x);
    __half2 q0 = __floats2half2_rn(h0, h1);
    __half2 q1 = __floats2half2_rn(h2, h3);
    uint2 hv;
    hv.x = *(uint32_t*)&q0;
    hv.y = *(uint32_t*)&q1;
    ((uint2*)g_xch)[i] = hv;
}

// ============================================================
// 4) output GEMM: y = h @ Wo^T   (M=128, N=128, fp16 single pass)
//    Per stage BK=64: A 16K | B 16K = 32K, x3 stages; 2 CTAs/SM
//    A loads via .ca (co-resident CTAs share m0); y stored fp16 into g_hap
// ============================================================
#define OUT_STAGE 32768
#define OUT_SMEM  98304

__global__ __launch_bounds__(256, 2)
void gemm_out_tc() {
    extern __shared__ char smem[];
    uint32_t sb = smem_u32(smem);
    int tid = threadIdx.x, wid = tid >> 5, lane = tid & 31;
    int m0 = blockIdx.y * 128;
    int n0 = blockIdx.x * 128;
    __half* yout = (__half*)g_hap;

    float acc[2][8][4] = {};

    auto issue = [&](int c) {
        uint32_t st = sb + (uint32_t)(c % 3) * OUT_STAGE;
        int k0 = c * 64;
        #pragma unroll
        for (int t = 0; t < 8; t++) {           // A,B: 128 rows x 8 granules each
            int idx = tid + t * 256;
            int sel = idx >> 10, r = (idx >> 3) & 127, g = idx & 7;
            if (sel) {
                cpasync16(st + 16384 + sw128(r * 128 + g * 16),
                          g_Woh + (size_t)(n0 + r) * Dq + k0 + g * 8);
            } else {
                cpasync16ca(st + sw128(r * 128 + g * 16),
                            g_xch + (size_t)(m0 + r) * Dq + k0 + g * 8);
            }
        }
    };

    int wm0 = (wid >> 1) * 32;
    int wn0 = (wid & 1) * 64;
    uint32_t aRowB = (uint32_t)(wm0 + (lane & 15)) * 128;
    uint32_t aColB = (uint32_t)(lane >> 4) * 16;
    uint32_t bRowB = (uint32_t)(((lane >> 4) << 3) + (lane & 7)) * 128;
    uint32_t bColB = (uint32_t)((lane >> 3) & 1) * 16;

    issue(0); CP_COMMIT();
    issue(1); CP_COMMIT();

    #pragma unroll 1
    for (int c = 0; c < 16; ++c) {
        if (c < 15) asm volatile("cp.async.wait_group 1;" ::: "memory");
        else        asm volatile("cp.async.wait_group 0;" ::: "memory");
        __syncthreads();
        uint32_t st = sb + (uint32_t)(c % 3) * OUT_STAGE;
        #pragma unroll
        for (int ks = 0; ks < 4; ++ks) {
            uint32_t ka = (uint32_t)ks * 32;
            uint32_t a0[4], a1[4];
            ldsm4(a0, st + sw128(aRowB + ka + aColB));
            ldsm4(a1, st + sw128(aRowB + 2048 + ka + aColB));
            #pragma unroll
            for (int half = 0; half < 2; half++) {
                uint32_t nbase = (uint32_t)(wn0 + half * 32) * 128;
                uint32_t bq[2][4];
                ldsm4(bq[0], st + 16384 + sw128(nbase + bRowB + ka + bColB));
                ldsm4(bq[1], st + 16384 + sw128(nbase + 2048 + bRowB + ka + bColB));
                #pragma unroll
                for (int j = 0; j < 4; ++j) {
                    int jj = half * 4 + j;
                    int nb = j >> 1, hh = (j & 1) * 2;
                    mma16816(acc[0][jj], a0, bq[nb][hh], bq[nb][hh + 1]);
                    mma16816(acc[1][jj], a1, bq[nb][hh], bq[nb][hh + 1]);
                }
            }
        }
        if (c < 14) { issue(c + 2); CP_COMMIT(); }
        __syncthreads();
    }

    // store y fp16 -> yout (half2 per acc pair)
    #pragma unroll
    for (int tm = 0; tm < 2; tm++)
        #pragma unroll
        for (int jj = 0; jj < 8; jj++) {
            int row = m0 + wm0 + tm * 16 + (lane >> 2);
            int col = n0 + wn0 + jj * 8 + (lane & 3) * 2;
            *(__half2*)&yout[(size_t)row * Dq + col] =
                __floats2half2_rn(acc[tm][jj][0], acc[tm][jj][1]);
            *(__half2*)&yout[(size_t)(row + 8) * Dq + col] =
                __floats2half2_rn(acc[tm][jj][2], acc[tm][jj][3]);
        }
}

// ============================================================
// 5) RMSNorm over D per row (reads y fp16, writes fp32 out)
// ============================================================
__global__ void rmsnorm_kernel(const float* __restrict__ nw, float* __restrict__ out) {
    int row = blockIdx.x;
    int tid = threadIdx.x;   // 256 threads, 4 elems each
    const __half* yout = (const __half*)g_hap;
    uint2 yv = ((const uint2*)yout)[(size_t)row * (Dq / 4) + tid];
    float2 y0 = __half22float2(*(__half2*)&yv.x);
    float2 y1 = __half22float2(*(__half2*)&yv.y);
    float ss = y0.x * y0.x + y0.y * y0.y + y1.x * y1.x + y1.y * y1.y;
    #pragma unroll
    for (int o = 16; o; o >>= 1) ss += __shfl_xor_sync(0xffffffffu, ss, o);
    __shared__ float sred[8];
    if ((tid & 31) == 0) sred[tid >> 5] = ss;
    __syncthreads();
    float tot = 0.f;
    #pragma unroll
    for (int w = 0; w < 8; w++) tot += sred[w];
    float s = rsqrtf(tot * (1.0f / Dq) + 1e-6f);
    float4 wv = ((const float4*)nw)[tid];
    float4 o4 = make_float4(y0.x * s * wv.x, y0.y * s * wv.y,
                            y1.x * s * wv.z, y1.y * s * wv.w);
    ((float4*)out)[(size_t)row * (Dq / 4) + tid] = o4;
}

// ============================================================
extern "C" void kernel_launch(void* const* d_in, const int* in_sizes, int n_in,
                              void* d_out, int out_size) {
    const float* x   = (const float*)d_in[0];
    const float* cw  = (const float*)d_in[1];
    const float* cb  = (const float*)d_in[2];
    const float* Wr  = (const float*)d_in[3];
    const float* Wrb = (const float*)d_in[4];
    const float* Wi  = (const float*)d_in[5];
    const float* Wib = (const float*)d_in[6];
    const float* la  = (const float*)d_in[7];
    const float* Wo  = (const float*)d_in[8];
    const float* nw  = (const float*)d_in[9];
    float* out = (float*)d_out;

    cudaFuncSetAttribute(gemm_ri_tc,  cudaFuncAttributeMaxDynamicSharedMemorySize, RI_SMEM);
    cudaFuncSetAttribute(gemm_out_tc, cudaFuncAttributeMaxDynamicSharedMemorySize, OUT_SMEM);

    conv_prep_kernel<<<WPREP_BLOCKS + CONV_BLOCKS, 256>>>(x, cw, cb, Wr, Wi, Wo);

    gemm_ri_tc<<<dim3(Dq / 64, Nq / 128), 256, RI_SMEM>>>(x, cw, cb, Wrb, Wib, la);

    scan2_kernel<<<dim3(Dq / 64, 1, Bq), 512>>>();
    scan3_kernel<<<(int)(((size_t)Nq * Dq / 4) / 256), 256>>>();

    gemm_out_tc<<<dim3(Dq / 128, Nq / 128), 256, OUT_SMEM>>>();

    rmsnorm_kernel<<<Nq, 256>>>(nw, out);
}

// round 16
// speedup vs baseline: 1.0609x; 1.0609x over previous
#include <cuda_runtime.h>
#include <cuda_fp16.h>
#include <math.h>
#include <stdint.h>

#define Bq 4
#define Lq 8192
#define Dq 1024
#define Nq (Bq*Lq)        // 32768 rows
#define KCONV 4
#define NC 64             // scan chunks per sequence (Lq/LC)
#define LC 128            // == GEMM row-tile M

// ---------------- scratch (device globals; no cudaMalloc allowed) ----------
__device__ __half  g_xch [(size_t)Nq*Dq];   // x_conv fp16  (later: h fp16)
__device__ __half2 g_hap [(size_t)Nq*Dq];   // (h_local, apre) fp16 pairs; later y fp16
__device__ float g_aggP[Bq*NC*Dq];
__device__ float g_aggS[Bq*NC*Dq];
__device__ float g_carry[Bq*NC*Dq];
__device__ __half g_Wrh[(size_t)Dq*Dq];
__device__ __half g_Wih[(size_t)Dq*Dq];
__device__ __half g_Woh[(size_t)Dq*Dq];

// ---------------- PTX helpers (all sm_80-compatible) ------------------------
__device__ __forceinline__ uint32_t smem_u32(const void* p) {
    uint32_t a;
    asm("{ .reg .u64 t; cvta.to.shared.u64 t, %1; cvt.u32.u64 %0, t; }" : "=r"(a) : "l"(p));
    return a;
}
__device__ __forceinline__ void ldsm4(uint32_t (&r)[4], uint32_t addr) {
    asm volatile("ldmatrix.sync.aligned.m8n8.x4.shared.b16 {%0,%1,%2,%3}, [%4];"
        : "=r"(r[0]), "=r"(r[1]), "=r"(r[2]), "=r"(r[3]) : "r"(addr));
}
__device__ __forceinline__ void mma16816(float (&d)[4], const uint32_t (&a)[4],
                                         uint32_t b0, uint32_t b1) {
    asm volatile("mma.sync.aligned.m16n8k16.row.col.f32.f16.f16.f32 "
        "{%0,%1,%2,%3}, {%4,%5,%6,%7}, {%8,%9}, {%0,%1,%2,%3};"
        : "+f"(d[0]), "+f"(d[1]), "+f"(d[2]), "+f"(d[3])
        : "r"(a[0]), "r"(a[1]), "r"(a[2]), "r"(a[3]), "r"(b0), "r"(b1));
}
__device__ __forceinline__ void cpasync16(uint32_t saddr, const void* g) {
    asm volatile("cp.async.cg.shared.global [%0], [%1], 16;" :: "r"(saddr), "l"(g));
}
#define CP_COMMIT() asm volatile("cp.async.commit_group;" ::: "memory")
__device__ __forceinline__ uint32_t sw128(uint32_t off) { return off ^ ((off >> 3) & 0x70); }

// ============================================================
// 0+1) fused: weight prep (fp32->fp16) + causal depthwise conv
//      first WPREP_BLOCKS blocks convert W; the rest run conv (16 l/thread)
// ============================================================
#define WPREP_BLOCKS (3 * Dq * Dq / 4 / 256)              // 3072
#define CONV_BLOCKS  ((Bq * (Lq / 16) * (Dq / 4) + 255) / 256)

__global__ void conv_prep_kernel(const float* __restrict__ x,
                                 const float* __restrict__ w,
                                 const float* __restrict__ bias,
                                 const float* __restrict__ Wr,
                                 const float* __restrict__ Wi,
                                 const float* __restrict__ Wo) {
    if (blockIdx.x < WPREP_BLOCKS) {
        int i = blockIdx.x * blockDim.x + threadIdx.x;    // float4 index
        const int Q = Dq * Dq / 4;
        int wsel = i / Q;
        int off = i - wsel * Q;
        const float4* src = (wsel == 0) ? (const float4*)Wr
                          : (wsel == 1) ? (const float4*)Wi : (const float4*)Wo;
        __half* dst = (wsel == 0) ? g_Wrh : (wsel == 1) ? g_Wih : g_Woh;
        float4 v = src[off];
        __half2 p0 = __floats2half2_rn(v.x, v.y);
        __half2 p1 = __floats2half2_rn(v.z, v.w);
        uint2 hv;
        hv.x = *(uint32_t*)&p0;
        hv.y = *(uint32_t*)&p1;
        ((uint2*)dst)[off] = hv;
        return;
    }

    const int D4 = Dq / 4;
    const int LG = Lq / 16;                // l-groups per sequence
    int t = (blockIdx.x - WPREP_BLOCKS) * blockDim.x + threadIdx.x;
    if (t >= Bq * LG * D4) return;
    int d4 = t % D4;
    int g  = t / D4;
    int b  = g / LG;
    int l0 = (g % LG) * 16;
    int n0 = b * Lq + l0;                  // first output row

    float wv[4][4];
    const float* wp = w + d4 * 16;
    #pragma unroll
    for (int dl = 0; dl < 4; dl++)
        #pragma unroll
        for (int k = 0; k < 4; k++) wv[dl][k] = wp[dl * 4 + k];
    float4 bb = ((const float4*)bias)[d4];

    // window rows l0-3 .. l0+15  (19 loads for 16 outputs)
    float4 xv[19];
    #pragma unroll
    for (int j = 0; j < 19; j++) {
        int l = l0 - 3 + j;
        if (l < 0) xv[j] = make_float4(0.f, 0.f, 0.f, 0.f);
        else       xv[j] = ((const float4*)x)[(size_t)(b * Lq + l) * D4 + d4];
    }

    #pragma unroll
    for (int i = 0; i < 16; i++) {
        float a0 = bb.x, a1 = bb.y, a2 = bb.z, a3 = bb.w;
        #pragma unroll
        for (int k = 0; k < 4; k++) {
            float4 v = xv[i + k];
            a0 = fmaf(v.x, wv[0][k], a0);
            a1 = fmaf(v.y, wv[1][k], a1);
            a2 = fmaf(v.z, wv[2][k], a2);
            a3 = fmaf(v.w, wv[3][k], a3);
        }
        __half2 p0 = __floats2half2_rn(a0, a1);
        __half2 p1 = __floats2half2_rn(a2, a3);
        uint2 hv;
        hv.x = *(uint32_t*)&p0;
        hv.y = *(uint32_t*)&p1;
        ((uint2*)g_xch)[(size_t)(n0 + i) * D4 + d4] = hv;
    }
}

// ============================================================
// 2) dual GEMM (r & i, fp16) + fused conv-recompute + gates + local scan
//    tile M=128, N=64.  Per stage BK=64: A 16K | Br 8K | Bi 8K = 32K, x3 stages
//    2 CTAs / SM; single-sync mainloop (R14 schedule, all .cg)
// ============================================================
#define RI_STAGE 32768
#define RI_SMEM  102400

__global__ __launch_bounds__(256, 2)
void gemm_ri_tc(const float* __restrict__ x,
                const float* __restrict__ cw, const float* __restrict__ cb,
                const float* __restrict__ Wrb, const float* __restrict__ Wib,
                const float* __restrict__ log_a) {
    extern __shared__ char smem[];
    __shared__ float  s_logab[64], s_rb[64], s_ib[64], s_cb[64];
    __shared__ float4 s_cw[64];
    __shared__ float  sPc[4][64], sSc[4][64];
    uint32_t sb = smem_u32(smem);
    int tid = threadIdx.x, wid = tid >> 5, lane = tid & 31;
    int m0 = blockIdx.y * 128;
    int n0 = blockIdx.x * 64;

    if (tid < 64) {
        float la = __ldg(&log_a[n0 + tid]);
        s_logab[tid] = -log1pf(expf(-la));     // ln(sigmoid(la)), tiny negative
        s_rb[tid]    = __ldg(&Wrb[n0 + tid]);
        s_ib[tid]    = __ldg(&Wib[n0 + tid]);
        s_cb[tid]    = __ldg(&cb[n0 + tid]);
        s_cw[tid]    = ((const float4*)cw)[n0 + tid];
    }

    float accR[2][4][4] = {}, accI[2][4][4] = {};

    auto issue = [&](int c) {
        uint32_t st = sb + (uint32_t)(c % 3) * RI_STAGE;
        int k0 = c * 64;
        #pragma unroll
        for (int t = 0; t < 4; t++) {           // A: 128 rows x 8 granules
            int idx = tid + t * 256;
            int r = idx >> 3, g = idx & 7;
            cpasync16(st + sw128(r * 128 + g * 16),
                      g_xch + (size_t)(m0 + r) * Dq + k0 + g * 8);
        }
        #pragma unroll
        for (int t = 0; t < 4; t++) {           // Br,Bi: 64 rows x 8 granules each
            int idx = tid + t * 256;
            int sel = idx >> 9, r = (idx >> 3) & 63, g = idx & 7;
            const __half* W = sel ? g_Wih : g_Wrh;
            cpasync16(st + 16384 + sel * 8192 + sw128(r * 128 + g * 16),
                      W + (size_t)(n0 + r) * Dq + k0 + g * 8);
        }
    };

    int wm0 = (wid >> 1) * 32;
    int wn0 = (wid & 1) * 32;
    uint32_t aRowB = (uint32_t)(wm0 + (lane & 15)) * 128;
    uint32_t aColB = (uint32_t)(lane >> 4) * 16;
    uint32_t bRowB = (uint32_t)(wn0 + ((lane >> 4) << 3) + (lane & 7)) * 128;
    uint32_t bColB = (uint32_t)((lane >> 3) & 1) * 16;

    issue(0); CP_COMMIT();
    issue(1); CP_COMMIT();

    #pragma unroll 1
    for (int c = 0; c < 16; ++c) {
        if (c < 15) asm volatile("cp.async.wait_group 1;" ::: "memory");
        else        asm volatile("cp.async.wait_group 0;" ::: "memory");
        __syncthreads();
        uint32_t st = sb + (uint32_t)(c % 3) * RI_STAGE;
        #pragma unroll
        for (int ks = 0; ks < 4; ++ks) {
            uint32_t ka = (uint32_t)ks * 32;
            uint32_t a0[4], a1[4], br[2][4], bi[2][4];
            ldsm4(a0, st + sw128(aRowB + ka + aColB));
            ldsm4(a1, st + sw128(aRowB + 2048 + ka + aColB));
            ldsm4(br[0], st + 16384 + sw128(bRowB + ka + bColB));
            ldsm4(br[1], st + 16384 + sw128(bRowB + 2048 + ka + bColB));
            ldsm4(bi[0], st + 24576 + sw128(bRowB + ka + bColB));
            ldsm4(bi[1], st + 24576 + sw128(bRowB + 2048 + ka + bColB));
            #pragma unroll
            for (int j = 0; j < 4; ++j) {
                int nb = j >> 1, hh = (j & 1) * 2;
                mma16816(accR[0][j], a0, br[nb][hh], br[nb][hh + 1]);
                mma16816(accR[1][j], a1, br[nb][hh], br[nb][hh + 1]);
                mma16816(accI[0][j], a0, bi[nb][hh], bi[nb][hh + 1]);
                mma16816(accI[1][j], a1, bi[nb][hh], bi[nb][hh + 1]);
            }
        }
        if (c < 14) { issue(c + 2); CP_COMMIT(); }
        __syncthreads();
    }

    // ---- epilogue overlay
    float* a_s = (float*)smem;            // [128][65]
    float* b_s = a_s + 128 * 65;          // [128][65]
    float* xs  = b_s + 128 * 65;          // [131][68] raw x tile (rows m0-3..m0+127)

    int bat0 = (m0 >> 13) << 13;          // first row of this sequence
    #pragma unroll
    for (int t = 0; t < 9; t++) {
        int idx = tid + t * 256;          // 131*16 = 2096 float4 loads
        if (idx < 131 * 16) {
            int j = idx >> 4, c4 = idx & 15;
            int gr = m0 - 3 + j;
            float4 v = make_float4(0.f, 0.f, 0.f, 0.f);
            if (gr >= bat0) v = *(const float4*)&x[(size_t)gr * Dq + n0 + c4 * 4];
            float* dst = &xs[j * 68 + c4 * 4];
            dst[0] = v.x; dst[1] = v.y; dst[2] = v.z; dst[3] = v.w;
        }
    }
    __syncthreads();

    #pragma unroll
    for (int tm = 0; tm < 2; tm++)
        #pragma unroll
        for (int j = 0; j < 4; j++) {
            int colb = wn0 + j * 8 + (lane & 3) * 2;
            #pragma unroll
            for (int e = 0; e < 4; e++) {
                int row = wm0 + tm * 16 + (lane >> 2) + (e >> 1) * 8;
                int col = colb + (e & 1);
                float4 wv = s_cw[col];
                float xcv = s_cb[col];
                xcv = fmaf(xs[(row + 0) * 68 + col], wv.x, xcv);
                xcv = fmaf(xs[(row + 1) * 68 + col], wv.y, xcv);
                xcv = fmaf(xs[(row + 2) * 68 + col], wv.z, xcv);
                xcv = fmaf(xs[(row + 3) * 68 + col], wv.w, xcv);
                float log_ab = s_logab[col];
                float crv = accR[tm][j][e] + s_rb[col];
                float civ = accI[tm][j][e] + s_ib[col];
                float r  = __fdividef(1.f, 1.f + __expf(-crv));
                float ii = __fdividef(1.f, 1.f + __expf(-civ));
                float t  = 8.f * r * log_ab;               // in (-0.00443, 0]
                // exp(t) and -expm1(2t): 3-term polys, exact to <3e-8 rel in range
                float a  = 1.f + t * (1.f + t * (0.5f + t * (1.f / 6.f)));
                float u  = 2.f * t;
                float om = -(u * (1.f + u * (0.5f + u * (1.f / 6.f))));
                om = fmaxf(om, 1e-6f);
                float bt = sqrtf(om) * ii * xcv;
                a_s[row * 65 + col] = a;
                b_s[row * 65 + col] = bt;
            }
        }
    __syncthreads();

    // ---- parallel local scan: 4 segments of 32 rows x 64 cols (fp32 math, fp16 store)
    {
        int seg = tid >> 6, cc = tid & 63;
        float P = 1.f, S = 0.f;
        #pragma unroll 8
        for (int l = seg * 32; l < seg * 32 + 32; l++) {
            float a = a_s[l * 65 + cc], b = b_s[l * 65 + cc];
            S = fmaf(a, S, b);
            P *= a;
        }
        sPc[seg][cc] = P; sSc[seg][cc] = S;
        __syncthreads();
        float cS = 0.f, cP = 1.f;
        #pragma unroll
        for (int g = 0; g < 3; g++)
            if (g < seg) { cS = fmaf(sPc[g][cc], cS, sSc[g][cc]); cP *= sPc[g][cc]; }
        float h = cS, Ap = cP;
        size_t gb = (size_t)(m0 + seg * 32) * Dq + n0 + cc;
        #pragma unroll 8
        for (int l = 0; l < 32; l++) {
            float a = a_s[(seg * 32 + l) * 65 + cc], b = b_s[(seg * 32 + l) * 65 + cc];
            h = fmaf(a, h, b);
            Ap *= a;
            g_hap[gb + (size_t)l * Dq] =
                __halves2half2(__float2half_rn(h), __float2half_rn(Ap));
        }
        if (seg == 3) {
            int bat = m0 >> 13, chk = (m0 & 8191) >> 7;
            int ai = (bat * NC + chk) * Dq + n0 + cc;
            g_aggP[ai] = Ap;
            g_aggS[ai] = h;
        }
    }
}

// ============================================================
// 3) inter-chunk scan (parallel: 8-chunk serial compose + smem combine)
// ============================================================
__global__ __launch_bounds__(512)
void scan2_kernel() {
    __shared__ float sP[8][65], sS[8][65];
    int d0 = blockIdx.x * 64;
    int b  = blockIdx.z;
    int d  = threadIdx.x & 63;
    int cg = threadIdx.x >> 6;            // 0..7

    float locP[8], locS[8];
    float P = 1.f, S = 0.f;
    #pragma unroll
    for (int j = 0; j < 8; j++) {
        int ai = (b * NC + cg * 8 + j) * Dq + d0 + d;
        locP[j] = g_aggP[ai];
        locS[j] = g_aggS[ai];
        S = fmaf(locP[j], S, locS[j]);
        P *= locP[j];
    }
    sP[cg][d] = P; sS[cg][d] = S;
    __syncthreads();

    float carry = 0.f;                    // exclusive combine over lower groups
    #pragma unroll
    for (int g = 0; g < 7; g++)
        if (g < cg) carry = fmaf(sP[g][d], carry, sS[g][d]);

    #pragma unroll
    for (int j = 0; j < 8; j++) {
        int ai = (b * NC + cg * 8 + j) * Dq + d0 + d;
        g_carry[ai] = carry;
        carry = fmaf(locP[j], carry, locS[j]);
    }
}

// ============================================================
// 3b) elementwise fixup -> h (fp16 into g_xch); reads (h,ap) pairs
// ============================================================
__global__ void scan3_kernel() {
    const int D4 = Dq / 4;
    size_t i = (size_t)blockIdx.x * blockDim.x + threadIdx.x;  // 4 elems each
    int d4  = (int)(i % D4);
    int row = (int)(i / D4);
    int bat = row >> 13;
    int chk = (row & 8191) >> 7;
    const float4 cy = *(const float4*)&g_carry[(bat * NC + chk) * Dq + d4 * 4];
    uint4 pv = ((const uint4*)g_hap)[i];     // 4 (h, ap) half2 pairs
    float2 e0 = __half22float2(*(__half2*)&pv.x);
    float2 e1 = __half22float2(*(__half2*)&pv.y);
    float2 e2 = __half22float2(*(__half2*)&pv.z);
    float2 e3 = __half22float2(*(__half2*)&pv.w);
    float h0 = fmaf(cy.x, e0.y, e0.x);
    float h1 = fmaf(cy.y, e1.y, e1.x);
    float h2 = fmaf(cy.z, e2.y, e2.x);
    float h3 = fmaf(cy.w, e3.y, e3.x);
    __half2 q0 = __floats2half2_rn(h0, h1);
    __half2 q1 = __floats2half2_rn(h2, h3);
    uint2 hv;
    hv.x = *(uint32_t*)&q0;
    hv.y = *(uint32_t*)&q1;
    ((uint2*)g_xch)[i] = hv;
}

// ============================================================
// 4) output GEMM: y = h @ Wo^T   (M=128, N=128, fp16 single pass)
//    Per stage BK=64: A 16K | B 16K = 32K, x3 stages; 2 CTAs/SM
//    R14 schedule (all .cg); y stored fp16 into g_hap
// ============================================================
#define OUT_STAGE 32768
#define OUT_SMEM  98304

__global__ __launch_bounds__(256, 2)
void gemm_out_tc() {
    extern __shared__ char smem[];
    uint32_t sb = smem_u32(smem);
    int tid = threadIdx.x, wid = tid >> 5, lane = tid & 31;
    int m0 = blockIdx.y * 128;
    int n0 = blockIdx.x * 128;
    __half* yout = (__half*)g_hap;

    float acc[2][8][4] = {};

    auto issue = [&](int c) {
        uint32_t st = sb + (uint32_t)(c % 3) * OUT_STAGE;
        int k0 = c * 64;
        #pragma unroll
        for (int t = 0; t < 8; t++) {           // A,B: 128 rows x 8 granules each
            int idx = tid + t * 256;
            int sel = idx >> 10, r = (idx >> 3) & 127, g = idx & 7;
            const __half* src = sel ? g_Woh + (size_t)(n0 + r) * Dq
                                    : g_xch + (size_t)(m0 + r) * Dq;
            cpasync16(st + sel * 16384 + sw128(r * 128 + g * 16), src + k0 + g * 8);
        }
    };

    int wm0 = (wid >> 1) * 32;
    int wn0 = (wid & 1) * 64;
    uint32_t aRowB = (uint32_t)(wm0 + (lane & 15)) * 128;
    uint32_t aColB = (uint32_t)(lane >> 4) * 16;
    uint32_t bRowB = (uint32_t)(((lane >> 4) << 3) + (lane & 7)) * 128;
    uint32_t bColB = (uint32_t)((lane >> 3) & 1) * 16;

    issue(0); CP_COMMIT();
    issue(1); CP_COMMIT();

    #pragma unroll 1
    for (int c = 0; c < 16; ++c) {
        if (c < 15) asm volatile("cp.async.wait_group 1;" ::: "memory");
        else        asm volatile("cp.async.wait_group 0;" ::: "memory");
        __syncthreads();
        uint32_t st = sb + (uint32_t)(c % 3) * OUT_STAGE;
        #pragma unroll
        for (int ks = 0; ks < 4; ++ks) {
            uint32_t ka = (uint32_t)ks * 32;
            uint32_t a0[4], a1[4];
            ldsm4(a0, st + sw128(aRowB + ka + aColB));
            ldsm4(a1, st + sw128(aRowB + 2048 + ka + aColB));
            #pragma unroll
            for (int half = 0; half < 2; half++) {
                uint32_t nbase = (uint32_t)(wn0 + half * 32) * 128;
                uint32_t bq[2][4];
                ldsm4(bq[0], st + 16384 + sw128(nbase + bRowB + ka + bColB));
                ldsm4(bq[1], st + 16384 + sw128(nbase + 2048 + bRowB + ka + bColB));
                #pragma unroll
                for (int j = 0; j < 4; ++j) {
                    int jj = half * 4 + j;
                    int nb = j >> 1, hh = (j & 1) * 2;
                    mma16816(acc[0][jj], a0, bq[nb][hh], bq[nb][hh + 1]);
                    mma16816(acc[1][jj], a1, bq[nb][hh], bq[nb][hh + 1]);
                }
            }
        }
        if (c < 14) { issue(c + 2); CP_COMMIT(); }
        __syncthreads();
    }

    // store y fp16 -> yout (half2 per acc pair)
    #pragma unroll
    for (int tm = 0; tm < 2; tm++)
        #pragma unroll
        for (int jj = 0; jj < 8; jj++) {
            int row = m0 + wm0 + tm * 16 + (lane >> 2);
            int col = n0 + wn0 + jj * 8 + (lane & 3) * 2;
            *(__half2*)&yout[(size_t)row * Dq + col] =
                __floats2half2_rn(acc[tm][jj][0], acc[tm][jj][1]);
            *(__half2*)&yout[(size_t)(row + 8) * Dq + col] =
                __floats2half2_rn(acc[tm][jj][2], acc[tm][jj][3]);
        }
}

// ============================================================
// 5) RMSNorm over D per row (reads y fp16, writes fp32 out)
// ============================================================
__global__ void rmsnorm_kernel(const float* __restrict__ nw, float* __restrict__ out) {
    int row = blockIdx.x;
    int tid = threadIdx.x;   // 256 threads, 4 elems each
    const __half* yout = (const __half*)g_hap;
    uint2 yv = ((const uint2*)yout)[(size_t)row * (Dq / 4) + tid];
    float2 y0 = __half22float2(*(__half2*)&yv.x);
    float2 y1 = __half22float2(*(__half2*)&yv.y);
    float ss = y0.x * y0.x + y0.y * y0.y + y1.x * y1.x + y1.y * y1.y;
    #pragma unroll
    for (int o = 16; o; o >>= 1) ss += __shfl_xor_sync(0xffffffffu, ss, o);
    __shared__ float sred[8];
    if ((tid & 31) == 0) sred[tid >> 5] = ss;
    __syncthreads();
    float tot = 0.f;
    #pragma unroll
    for (int w = 0; w < 8; w++) tot += sred[w];
    float s = rsqrtf(tot * (1.0f / Dq) + 1e-6f);
    float4 wv = ((const float4*)nw)[tid];
    float4 o4 = make_float4(y0.x * s * wv.x, y0.y * s * wv.y,
                            y1.x * s * wv.z, y1.y * s * wv.w);
    ((float4*)out)[(size_t)row * (Dq / 4) + tid] = o4;
}

// ============================================================
extern "C" void kernel_launch(void* const* d_in, const int* in_sizes, int n_in,
                              void* d_out, int out_size) {
    const float* x   = (const float*)d_in[0];
    const float* cw  = (const float*)d_in[1];
    const float* cb  = (const float*)d_in[2];
    const float* Wr  = (const float*)d_in[3];
    const float* Wrb = (const float*)d_in[4];
    const float* Wi  = (const float*)d_in[5];
    const float* Wib = (const float*)d_in[6];
    const float* la  = (const float*)d_in[7];
    const float* Wo  = (const float*)d_in[8];
    const float* nw  = (const float*)d_in[9];
    float* out = (float*)d_out;

    cudaFuncSetAttribute(gemm_ri_tc,  cudaFuncAttributeMaxDynamicSharedMemorySize, RI_SMEM);
    cudaFuncSetAttribute(gemm_out_tc, cudaFuncAttributeMaxDynamicSharedMemorySize, OUT_SMEM);

    conv_prep_kernel<<<WPREP_BLOCKS + CONV_BLOCKS, 256>>>(x, cw, cb, Wr, Wi, Wo);

    gemm_ri_tc<<<dim3(Dq / 64, Nq / 128), 256, RI_SMEM>>>(x, cw, cb, Wrb, Wib, la);

    scan2_kernel<<<dim3(Dq / 64, 1, Bq), 512>>>();
    scan3_kernel<<<(int)(((size_t)Nq * Dq / 4) / 256), 256>>>();

    gemm_out_tc<<<dim3(Dq / 128, Nq / 128), 256, OUT_SMEM>>>();

    rmsnorm_kernel<<<Nq, 256>>>(nw, out);
}

// round 17
// speedup vs baseline: 1.0652x; 1.0041x over previous
#include <cuda_runtime.h>
#include <cuda_fp16.h>
#include <math.h>
#include <stdint.h>

#define Bq 4
#define Lq 8192
#define Dq 1024
#define Nq (Bq*Lq)        // 32768 rows
#define KCONV 4
#define NC 64             // scan chunks per sequence (Lq/LC)
#define LC 128            // == GEMM row-tile M

// ---------------- scratch (device globals; no cudaMalloc allowed) ----------
__device__ __half  g_xch [(size_t)Nq*Dq];   // x_conv fp16  (later: h fp16)
__device__ __half2 g_hap [(size_t)Nq*Dq];   // (h_local, apre) fp16 pairs; later y fp16
__device__ float g_aggP[Bq*NC*Dq];
__device__ float g_aggS[Bq*NC*Dq];
__device__ float g_carry[Bq*NC*Dq];
__device__ __half g_Wrh[(size_t)Dq*Dq];
__device__ __half g_Wih[(size_t)Dq*Dq];
__device__ __half g_Woh[(size_t)Dq*Dq];

// ---------------- PTX helpers (all sm_80-compatible) ------------------------
__device__ __forceinline__ uint32_t smem_u32(const void* p) {
    uint32_t a;
    asm("{ .reg .u64 t; cvta.to.shared.u64 t, %1; cvt.u32.u64 %0, t; }" : "=r"(a) : "l"(p));
    return a;
}
__device__ __forceinline__ void ldsm4(uint32_t (&r)[4], uint32_t addr) {
    asm volatile("ldmatrix.sync.aligned.m8n8.x4.shared.b16 {%0,%1,%2,%3}, [%4];"
        : "=r"(r[0]), "=r"(r[1]), "=r"(r[2]), "=r"(r[3]) : "r"(addr));
}
__device__ __forceinline__ void mma16816(float (&d)[4], const uint32_t (&a)[4],
                                         uint32_t b0, uint32_t b1) {
    asm volatile("mma.sync.aligned.m16n8k16.row.col.f32.f16.f16.f32 "
        "{%0,%1,%2,%3}, {%4,%5,%6,%7}, {%8,%9}, {%0,%1,%2,%3};"
        : "+f"(d[0]), "+f"(d[1]), "+f"(d[2]), "+f"(d[3])
        : "r"(a[0]), "r"(a[1]), "r"(a[2]), "r"(a[3]), "r"(b0), "r"(b1));
}
__device__ __forceinline__ void cpasync16(uint32_t saddr, const void* g) {
    asm volatile("cp.async.cg.shared.global [%0], [%1], 16;" :: "r"(saddr), "l"(g));
}
#define CP_COMMIT() asm volatile("cp.async.commit_group;" ::: "memory")
__device__ __forceinline__ uint32_t sw128(uint32_t off) { return off ^ ((off >> 3) & 0x70); }

// ============================================================
// 0+1) fused: weight prep (fp32->fp16) + causal depthwise conv
//      first WPREP_BLOCKS blocks convert W; the rest run conv (16 l/thread)
// ============================================================
#define WPREP_BLOCKS (3 * Dq * Dq / 4 / 256)              // 3072
#define CONV_BLOCKS  ((Bq * (Lq / 16) * (Dq / 4) + 255) / 256)

__global__ void conv_prep_kernel(const float* __restrict__ x,
                                 const float* __restrict__ w,
                                 const float* __restrict__ bias,
                                 const float* __restrict__ Wr,
                                 const float* __restrict__ Wi,
                                 const float* __restrict__ Wo) {
    if (blockIdx.x < WPREP_BLOCKS) {
        int i = blockIdx.x * blockDim.x + threadIdx.x;    // float4 index
        const int Q = Dq * Dq / 4;
        int wsel = i / Q;
        int off = i - wsel * Q;
        const float4* src = (wsel == 0) ? (const float4*)Wr
                          : (wsel == 1) ? (const float4*)Wi : (const float4*)Wo;
        __half* dst = (wsel == 0) ? g_Wrh : (wsel == 1) ? g_Wih : g_Woh;
        float4 v = src[off];
        __half2 p0 = __floats2half2_rn(v.x, v.y);
        __half2 p1 = __floats2half2_rn(v.z, v.w);
        uint2 hv;
        hv.x = *(uint32_t*)&p0;
        hv.y = *(uint32_t*)&p1;
        ((uint2*)dst)[off] = hv;
        return;
    }

    const int D4 = Dq / 4;
    const int LG = Lq / 16;                // l-groups per sequence
    int t = (blockIdx.x - WPREP_BLOCKS) * blockDim.x + threadIdx.x;
    if (t >= Bq * LG * D4) return;
    int d4 = t % D4;
    int g  = t / D4;
    int b  = g / LG;
    int l0 = (g % LG) * 16;
    int n0 = b * Lq + l0;                  // first output row

    float wv[4][4];
    const float* wp = w + d4 * 16;
    #pragma unroll
    for (int dl = 0; dl < 4; dl++)
        #pragma unroll
        for (int k = 0; k < 4; k++) wv[dl][k] = wp[dl * 4 + k];
    float4 bb = ((const float4*)bias)[d4];

    // window rows l0-3 .. l0+15  (19 loads for 16 outputs)
    float4 xv[19];
    #pragma unroll
    for (int j = 0; j < 19; j++) {
        int l = l0 - 3 + j;
        if (l < 0) xv[j] = make_float4(0.f, 0.f, 0.f, 0.f);
        else       xv[j] = ((const float4*)x)[(size_t)(b * Lq + l) * D4 + d4];
    }

    #pragma unroll
    for (int i = 0; i < 16; i++) {
        float a0 = bb.x, a1 = bb.y, a2 = bb.z, a3 = bb.w;
        #pragma unroll
        for (int k = 0; k < 4; k++) {
            float4 v = xv[i + k];
            a0 = fmaf(v.x, wv[0][k], a0);
            a1 = fmaf(v.y, wv[1][k], a1);
            a2 = fmaf(v.z, wv[2][k], a2);
            a3 = fmaf(v.w, wv[3][k], a3);
        }
        __half2 p0 = __floats2half2_rn(a0, a1);
        __half2 p1 = __floats2half2_rn(a2, a3);
        uint2 hv;
        hv.x = *(uint32_t*)&p0;
        hv.y = *(uint32_t*)&p1;
        ((uint2*)g_xch)[(size_t)(n0 + i) * D4 + d4] = hv;
    }
}

// ============================================================
// 2) dual GEMM (r & i, fp16) + fused conv-recompute + gates + local scan
//    tile M=128, N=64.  Per stage BK=64: A 16K | Br 8K | Bi 8K = 32K, x3 stages
//    2 CTAs / SM; SINGLE-sync mainloop (write stage (c+2)%3 disjoint from reads c%3)
// ============================================================
#define RI_STAGE 32768
#define RI_SMEM  102400

__global__ __launch_bounds__(256, 2)
void gemm_ri_tc(const float* __restrict__ x,
                const float* __restrict__ cw, const float* __restrict__ cb,
                const float* __restrict__ Wrb, const float* __restrict__ Wib,
                const float* __restrict__ log_a) {
    extern __shared__ char smem[];
    __shared__ float  s_logab[64], s_rb[64], s_ib[64], s_cb[64];
    __shared__ float4 s_cw[64];
    __shared__ float  sPc[4][64], sSc[4][64];
    uint32_t sb = smem_u32(smem);
    int tid = threadIdx.x, wid = tid >> 5, lane = tid & 31;
    int m0 = blockIdx.y * 128;
    int n0 = blockIdx.x * 64;

    if (tid < 64) {
        float la = __ldg(&log_a[n0 + tid]);
        s_logab[tid] = -log1pf(expf(-la));     // ln(sigmoid(la)), tiny negative
        s_rb[tid]    = __ldg(&Wrb[n0 + tid]);
        s_ib[tid]    = __ldg(&Wib[n0 + tid]);
        s_cb[tid]    = __ldg(&cb[n0 + tid]);
        s_cw[tid]    = ((const float4*)cw)[n0 + tid];
    }

    float accR[2][4][4] = {}, accI[2][4][4] = {};

    auto issue = [&](int c) {
        uint32_t st = sb + (uint32_t)(c % 3) * RI_STAGE;
        int k0 = c * 64;
        #pragma unroll
        for (int t = 0; t < 4; t++) {           // A: 128 rows x 8 granules
            int idx = tid + t * 256;
            int r = idx >> 3, g = idx & 7;
            cpasync16(st + sw128(r * 128 + g * 16),
                      g_xch + (size_t)(m0 + r) * Dq + k0 + g * 8);
        }
        #pragma unroll
        for (int t = 0; t < 4; t++) {           // Br,Bi: 64 rows x 8 granules each
            int idx = tid + t * 256;
            int sel = idx >> 9, r = (idx >> 3) & 63, g = idx & 7;
            const __half* W = sel ? g_Wih : g_Wrh;
            cpasync16(st + 16384 + sel * 8192 + sw128(r * 128 + g * 16),
                      W + (size_t)(n0 + r) * Dq + k0 + g * 8);
        }
    };

    int wm0 = (wid >> 1) * 32;
    int wn0 = (wid & 1) * 32;
    uint32_t aRowB = (uint32_t)(wm0 + (lane & 15)) * 128;
    uint32_t aColB = (uint32_t)(lane >> 4) * 16;
    uint32_t bRowB = (uint32_t)(wn0 + ((lane >> 4) << 3) + (lane & 7)) * 128;
    uint32_t bColB = (uint32_t)((lane >> 3) & 1) * 16;

    issue(0); CP_COMMIT();
    issue(1); CP_COMMIT();

    #pragma unroll 1
    for (int c = 0; c < 16; ++c) {
        if (c < 15) asm volatile("cp.async.wait_group 1;" ::: "memory");
        else        asm volatile("cp.async.wait_group 0;" ::: "memory");
        __syncthreads();
        uint32_t st = sb + (uint32_t)(c % 3) * RI_STAGE;
        #pragma unroll
        for (int ks = 0; ks < 4; ++ks) {
            uint32_t ka = (uint32_t)ks * 32;
            uint32_t a0[4], a1[4], br[2][4], bi[2][4];
            ldsm4(a0, st + sw128(aRowB + ka + aColB));
            ldsm4(a1, st + sw128(aRowB + 2048 + ka + aColB));
            ldsm4(br[0], st + 16384 + sw128(bRowB + ka + bColB));
            ldsm4(br[1], st + 16384 + sw128(bRowB + 2048 + ka + bColB));
            ldsm4(bi[0], st + 24576 + sw128(bRowB + ka + bColB));
            ldsm4(bi[1], st + 24576 + sw128(bRowB + 2048 + ka + bColB));
            #pragma unroll
            for (int j = 0; j < 4; ++j) {
                int nb = j >> 1, hh = (j & 1) * 2;
                mma16816(accR[0][j], a0, br[nb][hh], br[nb][hh + 1]);
                mma16816(accR[1][j], a1, br[nb][hh], br[nb][hh + 1]);
                mma16816(accI[0][j], a0, bi[nb][hh], bi[nb][hh + 1]);
                mma16816(accI[1][j], a1, bi[nb][hh], bi[nb][hh + 1]);
            }
        }
        if (c < 14) { issue(c + 2); CP_COMMIT(); }
    }
    __syncthreads();   // protect smem before epilogue overlay

    // ---- epilogue overlay
    float* a_s = (float*)smem;            // [128][65]
    float* b_s = a_s + 128 * 65;          // [128][65]
    float* xs  = b_s + 128 * 65;          // [131][68] raw x tile (rows m0-3..m0+127)

    int bat0 = (m0 >> 13) << 13;          // first row of this sequence
    #pragma unroll
    for (int t = 0; t < 9; t++) {
        int idx = tid + t * 256;          // 131*16 = 2096 float4 loads
        if (idx < 131 * 16) {
            int j = idx >> 4, c4 = idx & 15;
            int gr = m0 - 3 + j;
            float4 v = make_float4(0.f, 0.f, 0.f, 0.f);
            if (gr >= bat0) v = *(const float4*)&x[(size_t)gr * Dq + n0 + c4 * 4];
            float* dst = &xs[j * 68 + c4 * 4];
            dst[0] = v.x; dst[1] = v.y; dst[2] = v.z; dst[3] = v.w;
        }
    }
    __syncthreads();

    #pragma unroll
    for (int tm = 0; tm < 2; tm++)
        #pragma unroll
        for (int j = 0; j < 4; j++) {
            int colb = wn0 + j * 8 + (lane & 3) * 2;
            #pragma unroll
            for (int e = 0; e < 4; e++) {
                int row = wm0 + tm * 16 + (lane >> 2) + (e >> 1) * 8;
                int col = colb + (e & 1);
                float4 wv = s_cw[col];
                float xcv = s_cb[col];
                xcv = fmaf(xs[(row + 0) * 68 + col], wv.x, xcv);
                xcv = fmaf(xs[(row + 1) * 68 + col], wv.y, xcv);
                xcv = fmaf(xs[(row + 2) * 68 + col], wv.z, xcv);
                xcv = fmaf(xs[(row + 3) * 68 + col], wv.w, xcv);
                float log_ab = s_logab[col];
                float crv = accR[tm][j][e] + s_rb[col];
                float civ = accI[tm][j][e] + s_ib[col];
                float r  = __fdividef(1.f, 1.f + __expf(-crv));
                float ii = __fdividef(1.f, 1.f + __expf(-civ));
                float t  = 8.f * r * log_ab;               // in (-0.00443, 0]
                // exp(t) and -expm1(2t): 3-term polys, exact to <3e-8 rel in range
                float a  = 1.f + t * (1.f + t * (0.5f + t * (1.f / 6.f)));
                float u  = 2.f * t;
                float om = -(u * (1.f + u * (0.5f + u * (1.f / 6.f))));
                om = fmaxf(om, 1e-6f);
                float bt = sqrtf(om) * ii * xcv;
                a_s[row * 65 + col] = a;
                b_s[row * 65 + col] = bt;
            }
        }
    __syncthreads();

    // ---- parallel local scan: 4 segments of 32 rows x 64 cols (fp32 math, fp16 store)
    {
        int seg = tid >> 6, cc = tid & 63;
        float P = 1.f, S = 0.f;
        #pragma unroll 8
        for (int l = seg * 32; l < seg * 32 + 32; l++) {
            float a = a_s[l * 65 + cc], b = b_s[l * 65 + cc];
            S = fmaf(a, S, b);
            P *= a;
        }
        sPc[seg][cc] = P; sSc[seg][cc] = S;
        __syncthreads();
        float cS = 0.f, cP = 1.f;
        #pragma unroll
        for (int g = 0; g < 3; g++)
            if (g < seg) { cS = fmaf(sPc[g][cc], cS, sSc[g][cc]); cP *= sPc[g][cc]; }
        float h = cS, Ap = cP;
        size_t gb = (size_t)(m0 + seg * 32) * Dq + n0 + cc;
        #pragma unroll 8
        for (int l = 0; l < 32; l++) {
            float a = a_s[(seg * 32 + l) * 65 + cc], b = b_s[(seg * 32 + l) * 65 + cc];
            h = fmaf(a, h, b);
            Ap *= a;
            g_hap[gb + (size_t)l * Dq] =
                __halves2half2(__float2half_rn(h), __float2half_rn(Ap));
        }
        if (seg == 3) {
            int bat = m0 >> 13, chk = (m0 & 8191) >> 7;
            int ai = (bat * NC + chk) * Dq + n0 + cc;
            g_aggP[ai] = Ap;
            g_aggS[ai] = h;
        }
    }
}

// ============================================================
// 3) inter-chunk scan (parallel: 8-chunk serial compose + smem combine)
// ============================================================
__global__ __launch_bounds__(512)
void scan2_kernel() {
    __shared__ float sP[8][65], sS[8][65];
    int d0 = blockIdx.x * 64;
    int b  = blockIdx.z;
    int d  = threadIdx.x & 63;
    int cg = threadIdx.x >> 6;            // 0..7

    float locP[8], locS[8];
    float P = 1.f, S = 0.f;
    #pragma unroll
    for (int j = 0; j < 8; j++) {
        int ai = (b * NC + cg * 8 + j) * Dq + d0 + d;
        locP[j] = g_aggP[ai];
        locS[j] = g_aggS[ai];
        S = fmaf(locP[j], S, locS[j]);
        P *= locP[j];
    }
    sP[cg][d] = P; sS[cg][d] = S;
    __syncthreads();

    float carry = 0.f;                    // exclusive combine over lower groups
    #pragma unroll
    for (int g = 0; g < 7; g++)
        if (g < cg) carry = fmaf(sP[g][d], carry, sS[g][d]);

    #pragma unroll
    for (int j = 0; j < 8; j++) {
        int ai = (b * NC + cg * 8 + j) * Dq + d0 + d;
        g_carry[ai] = carry;
        carry = fmaf(locP[j], carry, locS[j]);
    }
}

// ============================================================
// 3b) elementwise fixup -> h (fp16 into g_xch); reads (h,ap) pairs
// ============================================================
__global__ void scan3_kernel() {
    const int D4 = Dq / 4;
    size_t i = (size_t)blockIdx.x * blockDim.x + threadIdx.x;  // 4 elems each
    int d4  = (int)(i % D4);
    int row = (int)(i / D4);
    int bat = row >> 13;
    int chk = (row & 8191) >> 7;
    const float4 cy = *(const float4*)&g_carry[(bat * NC + chk) * Dq + d4 * 4];
    uint4 pv = ((const uint4*)g_hap)[i];     // 4 (h, ap) half2 pairs
    float2 e0 = __half22float2(*(__half2*)&pv.x);
    float2 e1 = __half22float2(*(__half2*)&pv.y);
    float2 e2 = __half22float2(*(__half2*)&pv.z);
    float2 e3 = __half22float2(*(__half2*)&pv.w);
    float h0 = fmaf(cy.x, e0.y, e0.x);
    float h1 = fmaf(cy.y, e1.y, e1.x);
    float h2 = fmaf(cy.z, e2.y, e2.x);
    float h3 = fmaf(cy.w, e3.y, e3.x);
    __half2 q0 = __floats2half2_rn(h0, h1);
    __half2 q1 = __floats2half2_rn(h2, h3);
    uint2 hv;
    hv.x = *(uint32_t*)&q0;
    hv.y = *(uint32_t*)&q1;
    ((uint2*)g_xch)[i] = hv;
}

// ============================================================
// 4) output GEMM: y = h @ Wo^T   (M=128, N=128, fp16 single pass)
//    Per stage BK=64: A 16K | B 16K = 32K, x3 stages; 2 CTAs/SM
//    SINGLE-sync mainloop; y stored fp16 into g_hap
// ============================================================
#define OUT_STAGE 32768
#define OUT_SMEM  98304

__global__ __launch_bounds__(256, 2)
void gemm_out_tc() {
    extern __shared__ char smem[];
    uint32_t sb = smem_u32(smem);
    int tid = threadIdx.x, wid = tid >> 5, lane = tid & 31;
    int m0 = blockIdx.y * 128;
    int n0 = blockIdx.x * 128;
    __half* yout = (__half*)g_hap;

    float acc[2][8][4] = {};

    auto issue = [&](int c) {
        uint32_t st = sb + (uint32_t)(c % 3) * OUT_STAGE;
        int k0 = c * 64;
        #pragma unroll
        for (int t = 0; t < 8; t++) {           // A,B: 128 rows x 8 granules each
            int idx = tid + t * 256;
            int sel = idx >> 10, r = (idx >> 3) & 127, g = idx & 7;
            const __half* src = sel ? g_Woh + (size_t)(n0 + r) * Dq
                                    : g_xch + (size_t)(m0 + r) * Dq;
            cpasync16(st + sel * 16384 + sw128(r * 128 + g * 16), src + k0 + g * 8);
        }
    };

    int wm0 = (wid >> 1) * 32;
    int wn0 = (wid & 1) * 64;
    uint32_t aRowB = (uint32_t)(wm0 + (lane & 15)) * 128;
    uint32_t aColB = (uint32_t)(lane >> 4) * 16;
    uint32_t bRowB = (uint32_t)(((lane >> 4) << 3) + (lane & 7)) * 128;
    uint32_t bColB = (uint32_t)((lane >> 3) & 1) * 16;

    issue(0); CP_COMMIT();
    issue(1); CP_COMMIT();

    #pragma unroll 1
    for (int c = 0; c < 16; ++c) {
        if (c < 15) asm volatile("cp.async.wait_group 1;" ::: "memory");
        else        asm volatile("cp.async.wait_group 0;" ::: "memory");
        __syncthreads();
        uint32_t st = sb + (uint32_t)(c % 3) * OUT_STAGE;
        #pragma unroll
        for (int ks = 0; ks < 4; ++ks) {
            uint32_t ka = (uint32_t)ks * 32;
            uint32_t a0[4], a1[4];
            ldsm4(a0, st + sw128(aRowB + ka + aColB));
            ldsm4(a1, st + sw128(aRowB + 2048 + ka + aColB));
            #pragma unroll
            for (int half = 0; half < 2; half++) {
                uint32_t nbase = (uint32_t)(wn0 + half * 32) * 128;
                uint32_t bq[2][4];
                ldsm4(bq[0], st + 16384 + sw128(nbase + bRowB + ka + bColB));
                ldsm4(bq[1], st + 16384 + sw128(nbase + 2048 + bRowB + ka + bColB));
                #pragma unroll
                for (int j = 0; j < 4; ++j) {
                    int jj = half * 4 + j;
                    int nb = j >> 1, hh = (j & 1) * 2;
                    mma16816(acc[0][jj], a0, bq[nb][hh], bq[nb][hh + 1]);
                    mma16816(acc[1][jj], a1, bq[nb][hh], bq[nb][hh + 1]);
                }
            }
        }
        if (c < 14) { issue(c + 2); CP_COMMIT(); }
    }

    // store y fp16 -> yout (half2 per acc pair); registers only, no sync needed
    #pragma unroll
    for (int tm = 0; tm < 2; tm++)
        #pragma unroll
        for (int jj = 0; jj < 8; jj++) {
            int row = m0 + wm0 + tm * 16 + (lane >> 2);
            int col = n0 + wn0 + jj * 8 + (lane & 3) * 2;
            *(__half2*)&yout[(size_t)row * Dq + col] =
                __floats2half2_rn(acc[tm][jj][0], acc[tm][jj][1]);
            *(__half2*)&yout[(size_t)(row + 8) * Dq + col] =
                __floats2half2_rn(acc[tm][jj][2], acc[tm][jj][3]);
        }
}

// ============================================================
// 5) RMSNorm over D per row (reads y fp16, writes fp32 out)
// ============================================================
__global__ void rmsnorm_kernel(const float* __restrict__ nw, float* __restrict__ out) {
    int row = blockIdx.x;
    int tid = threadIdx.x;   // 256 threads, 4 elems each
    const __half* yout = (const __half*)g_hap;
    uint2 yv = ((const uint2*)yout)[(size_t)row * (Dq / 4) + tid];
    float2 y0 = __half22float2(*(__half2*)&yv.x);
    float2 y1 = __half22float2(*(__half2*)&yv.y);
    float ss = y0.x * y0.x + y0.y * y0.y + y1.x * y1.x + y1.y * y1.y;
    #pragma unroll
    for (int o = 16; o; o >>= 1) ss += __shfl_xor_sync(0xffffffffu, ss, o);
    __shared__ float sred[8];
    if ((tid & 31) == 0) sred[tid >> 5] = ss;
    __syncthreads();
    float tot = 0.f;
    #pragma unroll
    for (int w = 0; w < 8; w++) tot += sred[w];
    float s = rsqrtf(tot * (1.0f / Dq) + 1e-6f);
    float4 wv = ((const float4*)nw)[tid];
    float4 o4 = make_float4(y0.x * s * wv.x, y0.y * s * wv.y,
                            y1.x * s * wv.z, y1.y * s * wv.w);
    ((float4*)out)[(size_t)row * (Dq / 4) + tid] = o4;
}

// ============================================================
extern "C" void kernel_launch(void* const* d_in, const int* in_sizes, int n_in,
                              void* d_out, int out_size) {
    const float* x   = (const float*)d_in[0];
    const float* cw  = (const float*)d_in[1];
    const float* cb  = (const float*)d_in[2];
    const float* Wr  = (const float*)d_in[3];
    const float* Wrb = (const float*)d_in[4];
    const float* Wi  = (const float*)d_in[5];
    const float* Wib = (const float*)d_in[6];
    const float* la  = (const float*)d_in[7];
    const float* Wo  = (const float*)d_in[8];
    const float* nw  = (const float*)d_in[9];
    float* out = (float*)d_out;

    cudaFuncSetAttribute(gemm_ri_tc,  cudaFuncAttributeMaxDynamicSharedMemorySize, RI_SMEM);
    cudaFuncSetAttribute(gemm_out_tc, cudaFuncAttributeMaxDynamicSharedMemorySize, OUT_SMEM);

    conv_prep_kernel<<<WPREP_BLOCKS + CONV_BLOCKS, 256>>>(x, cw, cb, Wr, Wi, Wo);

    gemm_ri_tc<<<dim3(Dq / 64, Nq / 128), 256, RI_SMEM>>>(x, cw, cb, Wrb, Wib, la);

    scan2_kernel<<<dim3(Dq / 64, 1, Bq), 512>>>();
    scan3_kernel<<<(int)(((size_t)Nq * Dq / 4) / 256), 256>>>();

    gemm_out_tc<<<dim3(Dq / 128, Nq / 128), 256, OUT_SMEM>>>();

    rmsnorm_kernel<<<Nq, 256>>>(nw, out);
}